// round 1
// baseline (speedup 1.0000x reference)
#include <cuda_runtime.h>
#include <math.h>

#define NN 100000
#define NE 1600000
#define HD 128
#define DOUT 40
#define BN_EPS 1e-5f
#define GB 782        // ceil(NN/128)
#define WARP_BLOCKS 12500  // NN*32/256

// ---------------- scratch (static device allocations only) ----------------
__device__ __align__(16) float g_bufA[(size_t)NN * HD];
__device__ __align__(16) float g_bufB[(size_t)NN * HD];
__device__ __align__(16) float g_bufC[(size_t)NN * HD];
__device__ int g_deg[NN];
__device__ int g_rowptr[NN + 1];
__device__ int g_cursor[NN];
__device__ int g_col[NE];
__device__ float g_sum[HD];
__device__ float g_sumsq[HD];
__device__ __align__(16) float g_scale[HD];
__device__ __align__(16) float g_shift[HD];

// ---------------- CSR build ----------------
__global__ void k_zero_deg() {
    int i = blockIdx.x * 256 + threadIdx.x;
    if (i < NN) g_deg[i] = 0;
}

__global__ void k_hist(const int* __restrict__ dst) {
    int e = blockIdx.x * 256 + threadIdx.x;
    if (e < NE) atomicAdd(&g_deg[dst[e]], 1);
}

__global__ void k_scan() {
    __shared__ int sh[1024];
    int t = threadIdx.x;
    const int chunk = (NN + 1023) / 1024;  // 98
    int beg = t * chunk;
    int end = min(beg + chunk, NN);
    int s = 0;
    for (int i = beg; i < end; i++) s += g_deg[i];
    sh[t] = s;
    __syncthreads();
    for (int off = 1; off < 1024; off <<= 1) {
        int v = (t >= off) ? sh[t - off] : 0;
        __syncthreads();
        sh[t] += v;
        __syncthreads();
    }
    int prefix = (t == 0) ? 0 : sh[t - 1];
    for (int i = beg; i < end; i++) {
        g_rowptr[i] = prefix;
        g_cursor[i] = prefix;
        prefix += g_deg[i];
    }
    if (t == 0) g_rowptr[NN] = NE;
}

__global__ void k_scatter(const int* __restrict__ src, const int* __restrict__ dst) {
    int e = blockIdx.x * 256 + threadIdx.x;
    if (e < NE) {
        int d = dst[e];
        int p = atomicAdd(&g_cursor[d], 1);
        g_col[p] = src[e];
    }
}

// ---------------- aggregation: warp per node ----------------
// MODE 0: mean over incoming neighbors (0 for isolated)
// MODE 1: self + sum over incoming neighbors (GIN, eps=0)
template <int MODE>
__global__ __launch_bounds__(256) void k_agg(const float* __restrict__ X,
                                             float* __restrict__ O) {
    int gw = (blockIdx.x * blockDim.x + threadIdx.x) >> 5;
    if (gw >= NN) return;
    int lane = threadIdx.x & 31;
    int beg = g_rowptr[gw], end = g_rowptr[gw + 1];
    float4 acc = make_float4(0.f, 0.f, 0.f, 0.f);
    for (int eb = beg; eb < end; eb += 32) {
        int n = min(32, end - eb);
        int ci = (eb + lane < end) ? g_col[eb + lane] : 0;
        for (int j = 0; j < n; j++) {
            int s = __shfl_sync(0xffffffffu, ci, j);
            float4 v = __ldg((const float4*)(X + (size_t)s * HD) + lane);
            acc.x += v.x; acc.y += v.y; acc.z += v.z; acc.w += v.w;
        }
    }
    if (MODE == 0) {
        int d = end - beg;
        float dd = (float)(d > 1 ? d : 1);
        acc.x /= dd; acc.y /= dd; acc.z /= dd; acc.w /= dd;
    } else {
        float4 v = __ldg((const float4*)(X + (size_t)gw * HD) + lane);
        acc.x += v.x; acc.y += v.y; acc.z += v.z; acc.w += v.w;
    }
    ((float4*)(O + (size_t)gw * HD))[lane] = acc;
}

// ---------------- dual GEMM: C = A1@W1 + A2@W2 + bias, optional relu ------
// A: [NN,128] row-major, W: [128,128] row-major (k-major rows), C: [NN,128]
template <bool RELU>
__global__ __launch_bounds__(256) void k_gemm128(
    const float* __restrict__ A1, const float* __restrict__ W1,
    const float* __restrict__ A2, const float* __restrict__ W2,
    const float* __restrict__ bias, float* __restrict__ C) {
    __shared__ float As[128 * 33];   // padded rows: stride 33, kills bank conflicts
    __shared__ float Ws[32 * 128];
    const int t = threadIdx.x;
    const int tx = t & 15, ty = t >> 4;
    const int row0 = blockIdx.x * 128;
    float acc[8][8];
#pragma unroll
    for (int i = 0; i < 8; i++)
#pragma unroll
        for (int j = 0; j < 8; j++) acc[i][j] = 0.f;

    for (int pass = 0; pass < 2; ++pass) {
        const float* A = pass ? A2 : A1;
        const float* W = pass ? W2 : W1;
        if (A == nullptr) continue;
        for (int kb = 0; kb < 4; ++kb) {
            const int k0 = kb * 32;
            // load A tile: 128 rows x 32 cols (padded)
#pragma unroll
            for (int it = 0; it < 4; ++it) {
                int lin = t + it * 256;        // 1024 float4s
                int m = lin >> 3, q = lin & 7; // 8 float4 per row
                float4 v = make_float4(0.f, 0.f, 0.f, 0.f);
                int r = row0 + m;
                if (r < NN) v = __ldg((const float4*)(A + (size_t)r * HD + k0) + q);
                As[m * 33 + q * 4 + 0] = v.x;
                As[m * 33 + q * 4 + 1] = v.y;
                As[m * 33 + q * 4 + 2] = v.z;
                As[m * 33 + q * 4 + 3] = v.w;
            }
            // load W tile: 32 rows x 128 cols
#pragma unroll
            for (int it = 0; it < 4; ++it) {
                int lin = t + it * 256;
                int m = lin >> 5, q = lin & 31;
                ((float4*)(Ws + m * 128))[q] =
                    __ldg((const float4*)(W + (size_t)(k0 + m) * HD) + q);
            }
            __syncthreads();
#pragma unroll 8
            for (int k = 0; k < 32; ++k) {
                float4 w0 = ((const float4*)(Ws + k * 128))[tx * 2];
                float4 w1 = ((const float4*)(Ws + k * 128))[tx * 2 + 1];
                float w[8] = {w0.x, w0.y, w0.z, w0.w, w1.x, w1.y, w1.z, w1.w};
                float a[8];
#pragma unroll
                for (int i = 0; i < 8; i++) a[i] = As[(ty * 8 + i) * 33 + k];
#pragma unroll
                for (int i = 0; i < 8; i++)
#pragma unroll
                    for (int j = 0; j < 8; j++)
                        acc[i][j] = fmaf(a[i], w[j], acc[i][j]);
            }
            __syncthreads();
        }
    }
    float b[8];
#pragma unroll
    for (int j = 0; j < 8; j++) b[j] = bias[tx * 8 + j];
#pragma unroll
    for (int i = 0; i < 8; i++) {
        int r = row0 + ty * 8 + i;
        if (r < NN) {
            float o[8];
#pragma unroll
            for (int j = 0; j < 8; j++) {
                float v = acc[i][j] + b[j];
                if (RELU) v = fmaxf(v, 0.f);
                o[j] = v;
            }
            float4* d4 = (float4*)(C + (size_t)r * HD + tx * 8);
            d4[0] = make_float4(o[0], o[1], o[2], o[3]);
            d4[1] = make_float4(o[4], o[5], o[6], o[7]);
        }
    }
}

// ---------------- final dual GEMM: [NN,128]@[128,40] x2 + bias ------------
__global__ __launch_bounds__(256) void k_gemm40(
    const float* __restrict__ A1, const float* __restrict__ W1,
    const float* __restrict__ A2, const float* __restrict__ W2,
    const float* __restrict__ bias, float* __restrict__ C) {
    __shared__ float As[128 * 33];
    __shared__ float Ws[32 * 40];
    const int t = threadIdx.x;
    const int tx = t & 7;   // 8 col groups * 5 cols
    const int ty = t >> 3;  // 32 row groups * 4 rows
    const int row0 = blockIdx.x * 128;
    float acc[4][5];
#pragma unroll
    for (int i = 0; i < 4; i++)
#pragma unroll
        for (int j = 0; j < 5; j++) acc[i][j] = 0.f;

    for (int pass = 0; pass < 2; ++pass) {
        const float* A = pass ? A2 : A1;
        const float* W = pass ? W2 : W1;
        for (int kb = 0; kb < 4; ++kb) {
            const int k0 = kb * 32;
#pragma unroll
            for (int it = 0; it < 4; ++it) {
                int lin = t + it * 256;
                int m = lin >> 3, q = lin & 7;
                float4 v = make_float4(0.f, 0.f, 0.f, 0.f);
                int r = row0 + m;
                if (r < NN) v = __ldg((const float4*)(A + (size_t)r * HD + k0) + q);
                As[m * 33 + q * 4 + 0] = v.x;
                As[m * 33 + q * 4 + 1] = v.y;
                As[m * 33 + q * 4 + 2] = v.z;
                As[m * 33 + q * 4 + 3] = v.w;
            }
            // W tile: 32 x 40 = 320 float4
#pragma unroll
            for (int it = 0; it < 2; ++it) {
                int lin = t + it * 256;
                if (lin < 320) {
                    int m = lin / 10, q = lin % 10;
                    ((float4*)(Ws + m * 40))[q] =
                        __ldg((const float4*)(W + (size_t)(k0 + m) * DOUT) + q);
                }
            }
            __syncthreads();
#pragma unroll 8
            for (int k = 0; k < 32; ++k) {
                float w[5];
#pragma unroll
                for (int j = 0; j < 5; j++) w[j] = Ws[k * 40 + tx * 5 + j];
                float a[4];
#pragma unroll
                for (int i = 0; i < 4; i++) a[i] = As[(ty * 4 + i) * 33 + k];
#pragma unroll
                for (int i = 0; i < 4; i++)
#pragma unroll
                    for (int j = 0; j < 5; j++)
                        acc[i][j] = fmaf(a[i], w[j], acc[i][j]);
            }
            __syncthreads();
        }
    }
    float b[5];
#pragma unroll
    for (int j = 0; j < 5; j++) b[j] = bias[tx * 5 + j];
#pragma unroll
    for (int i = 0; i < 4; i++) {
        int r = row0 + ty * 4 + i;
        if (r < NN) {
#pragma unroll
            for (int j = 0; j < 5; j++)
                C[(size_t)r * DOUT + tx * 5 + j] = acc[i][j] + b[j];
        }
    }
}

// ---------------- BatchNorm (batch statistics) ----------------
__global__ void k_bn_zero() {
    int c = threadIdx.x;
    g_sum[c] = 0.f;
    g_sumsq[c] = 0.f;
}

__global__ __launch_bounds__(256) void k_bn_stats(const float* __restrict__ X) {
    __shared__ float sh[256];
    int t = threadIdx.x;
    int c = t & 127, half = t >> 7;
    int row0 = blockIdx.x * 128;
    float s = 0.f, ss = 0.f;
    for (int i = half; i < 128; i += 2) {
        int r = row0 + i;
        if (r < NN) {
            float v = X[(size_t)r * HD + c];
            s += v;
            ss = fmaf(v, v, ss);
        }
    }
    sh[t] = s;
    __syncthreads();
    if (half == 0) atomicAdd(&g_sum[c], s + sh[128 + c]);
    __syncthreads();
    sh[t] = ss;
    __syncthreads();
    if (half == 0) atomicAdd(&g_sumsq[c], ss + sh[128 + c]);
}

__global__ void k_bn_finalize(const float* __restrict__ gamma,
                              const float* __restrict__ beta, int layer) {
    int c = threadIdx.x;
    float mean = g_sum[c] * (1.0f / NN);
    float var = g_sumsq[c] * (1.0f / NN) - mean * mean;
    float sc = gamma[layer * HD + c] * rsqrtf(var + BN_EPS);
    g_scale[c] = sc;
    g_shift[c] = fmaf(-mean, sc, beta[layer * HD + c]);
}

// y = relu(x*scale + shift) (+ residual)
template <bool RES>
__global__ __launch_bounds__(256) void k_bn_apply(const float* __restrict__ X,
                                                  const float* __restrict__ R,
                                                  float* __restrict__ O) {
    int idx = blockIdx.x * 256 + threadIdx.x;  // float4 index; exact NN*32
    if (idx >= NN * 32) return;
    int c4 = idx & 31;
    float4 v = ((const float4*)X)[idx];
    float4 sc = ((const float4*)g_scale)[c4];
    float4 sf = ((const float4*)g_shift)[c4];
    v.x = fmaxf(fmaf(v.x, sc.x, sf.x), 0.f);
    v.y = fmaxf(fmaf(v.y, sc.y, sf.y), 0.f);
    v.z = fmaxf(fmaf(v.z, sc.z, sf.z), 0.f);
    v.w = fmaxf(fmaf(v.w, sc.w, sf.w), 0.f);
    if (RES) {
        float4 r = ((const float4*)R)[idx];
        v.x += r.x; v.y += r.y; v.z += r.z; v.w += r.w;
    }
    ((float4*)O)[idx] = v;
}

// ---------------- row-wise log_softmax over 40 cols ----------------
__global__ __launch_bounds__(256) void k_logsoftmax(const float* __restrict__ X,
                                                    float* __restrict__ O) {
    int w = (blockIdx.x * 256 + threadIdx.x) >> 5;
    if (w >= NN) return;
    int lane = threadIdx.x & 31;
    const float* row = X + (size_t)w * DOUT;
    float v0 = (lane < DOUT) ? row[lane] : -INFINITY;
    float v1 = (lane + 32 < DOUT) ? row[lane + 32] : -INFINITY;
    float m = fmaxf(v0, v1);
#pragma unroll
    for (int o = 16; o; o >>= 1) m = fmaxf(m, __shfl_xor_sync(0xffffffffu, m, o));
    float s = expf(v0 - m) + ((lane + 32 < DOUT) ? expf(v1 - m) : 0.f);
#pragma unroll
    for (int o = 16; o; o >>= 1) s += __shfl_xor_sync(0xffffffffu, s, o);
    float l = m + logf(s);
    if (lane < DOUT) O[(size_t)w * DOUT + lane] = v0 - l;
    if (lane + 32 < DOUT) O[(size_t)w * DOUT + lane + 32] = v1 - l;
}

// ---------------- launch ----------------
extern "C" void kernel_launch(void* const* d_in, const int* in_sizes, int n_in,
                              void* d_out, int out_size) {
    const float* x    = (const float*)d_in[0];
    const int*   ei   = (const int*)d_in[1];
    const int*   src  = ei;
    const int*   dst  = ei + NE;
    const float* s0wl = (const float*)d_in[2];
    const float* s0wr = (const float*)d_in[3];
    const float* s0b  = (const float*)d_in[4];
    const float* gw1  = (const float*)d_in[5];
    const float* gb1  = (const float*)d_in[6];
    const float* gw2  = (const float*)d_in[7];
    const float* gb2  = (const float*)d_in[8];
    const float* s2wl = (const float*)d_in[9];
    const float* s2wr = (const float*)d_in[10];
    const float* s2b  = (const float*)d_in[11];
    const float* fwl  = (const float*)d_in[12];
    const float* fwr  = (const float*)d_in[13];
    const float* fb   = (const float*)d_in[14];
    const float* gamma = (const float*)d_in[15];
    const float* beta  = (const float*)d_in[16];
    float* out = (float*)d_out;

    void* p;
    cudaGetSymbolAddress(&p, g_bufA); float* A = (float*)p;
    cudaGetSymbolAddress(&p, g_bufB); float* B = (float*)p;
    cudaGetSymbolAddress(&p, g_bufC); float* C = (float*)p;

    // CSR build (per launch; deterministic work)
    k_zero_deg<<<(NN + 255) / 256, 256>>>();
    k_hist<<<(NE + 255) / 256, 256>>>(dst);
    k_scan<<<1, 1024>>>();
    k_scatter<<<(NE + 255) / 256, 256>>>(src, dst);

    // Layer 0: SAGE(x) -> BN -> ReLU          h := C
    k_agg<0><<<WARP_BLOCKS, 256>>>(x, A);
    k_gemm128<false><<<GB, 256>>>(A, s0wl, x, s0wr, s0b, B);
    k_bn_zero<<<1, 128>>>();
    k_bn_stats<<<GB, 256>>>(B);
    k_bn_finalize<<<1, 128>>>(gamma, beta, 0);
    k_bn_apply<false><<<WARP_BLOCKS, 256>>>(B, nullptr, C);

    // Layer 1: GIN -> BN -> ReLU -> +res      h := B
    k_agg<1><<<WARP_BLOCKS, 256>>>(C, A);                       // h + sum_agg(h)
    k_gemm128<true><<<GB, 256>>>(A, gw1, nullptr, nullptr, gb1, B);   // relu(.@w1+b1)
    k_gemm128<false><<<GB, 256>>>(B, gw2, nullptr, nullptr, gb2, A);  // .@w2+b2
    k_bn_zero<<<1, 128>>>();
    k_bn_stats<<<GB, 256>>>(A);
    k_bn_finalize<<<1, 128>>>(gamma, beta, 1);
    k_bn_apply<true><<<WARP_BLOCKS, 256>>>(A, C, B);

    // Layer 2: SAGE -> BN -> ReLU -> +res     h := A
    k_agg<0><<<WARP_BLOCKS, 256>>>(B, A);
    k_gemm128<false><<<GB, 256>>>(A, s2wl, B, s2wr, s2b, C);
    k_bn_zero<<<1, 128>>>();
    k_bn_stats<<<GB, 256>>>(C);
    k_bn_finalize<<<1, 128>>>(gamma, beta, 2);
    k_bn_apply<true><<<WARP_BLOCKS, 256>>>(C, B, A);

    // Final: SAGE(H->40) + log_softmax
    k_agg<0><<<WARP_BLOCKS, 256>>>(A, B);
    k_gemm40<<<GB, 256>>>(B, fwl, A, fwr, fb, C);  // C reused as [NN,40]
    k_logsoftmax<<<WARP_BLOCKS, 256>>>(C, out);
}

// round 3
// speedup vs baseline: 1.2358x; 1.2358x over previous
#include <cuda_runtime.h>
#include <cuda_bf16.h>
#include <math.h>
#include <stdint.h>

#define NN 100000
#define NE 1600000
#define HD 128
#define DOUT 40
#define BN_EPS 1e-5f
#define GB 782             // ceil(NN/128)
#define WARP_BLOCKS 12500  // NN*32/256

// ======================= scratch (static device memory) =======================
__device__ __align__(16) float g_bufA[(size_t)NN * HD];
__device__ __align__(16) float g_bufB[(size_t)NN * HD];
__device__ __align__(16) float g_bufC[(size_t)NN * HD];
__device__ int g_deg[NN];
__device__ int g_rowptr[NN + 1];
__device__ int g_cursor[NN];
__device__ int g_col[NE];
__device__ float g_sum[HD];
__device__ float g_sumsq[HD];
__device__ __align__(16) float g_scale[HD];
__device__ __align__(16) float g_shift[HD];
// weight images: transposed (Wt[n][k]), bf16, padded rows of 136 ushorts (272 B)
// 6 x [128-row image] hi/lo  +  2 x [48-row image] hi/lo (rows 40..47 stay zero)
#define IMGU 17408  // 128*136 ushorts
#define IMG40U 6528 // 48*136 ushorts
__device__ __align__(16) unsigned short g_wi[12 * IMGU];
__device__ __align__(16) unsigned short g_wi40[4 * IMG40U];

// ======================= helpers =======================
__device__ __forceinline__ uint32_t smem_u32(const void* p) {
    uint32_t a;
    asm("{ .reg .u64 t; cvta.to.shared.u64 t, %1; cvt.u32.u64 %0, t; }" : "=r"(a) : "l"(p));
    return a;
}
__device__ __forceinline__ void ldsm4(uint32_t* r, uint32_t addr) {
    asm volatile("ldmatrix.sync.aligned.m8n8.x4.shared.b16 {%0,%1,%2,%3}, [%4];"
                 : "=r"(r[0]), "=r"(r[1]), "=r"(r[2]), "=r"(r[3]) : "r"(addr));
}
__device__ __forceinline__ void mma_bf16(float* c, uint32_t a0, uint32_t a1, uint32_t a2,
                                         uint32_t a3, uint32_t b0, uint32_t b1) {
    asm volatile(
        "mma.sync.aligned.m16n8k16.row.col.f32.bf16.bf16.f32 "
        "{%0,%1,%2,%3}, {%4,%5,%6,%7}, {%8,%9}, {%0,%1,%2,%3};"
        : "+f"(c[0]), "+f"(c[1]), "+f"(c[2]), "+f"(c[3])
        : "r"(a0), "r"(a1), "r"(a2), "r"(a3), "r"(b0), "r"(b1));
}
__device__ __forceinline__ void splitpair(float2 v, uint32_t& h, uint32_t& l) {
    __nv_bfloat162 hb = __float22bfloat162_rn(v);
    float2 hf = __bfloat1622float2(hb);
    __nv_bfloat162 lb = __float22bfloat162_rn(make_float2(v.x - hf.x, v.y - hf.y));
    h = *reinterpret_cast<uint32_t*>(&hb);
    l = *reinterpret_cast<uint32_t*>(&lb);
}

// ======================= CSR build =======================
__global__ void k_zero_deg() {
    int i = blockIdx.x * 256 + threadIdx.x;
    if (i < NN) g_deg[i] = 0;
}
__global__ void k_hist(const int* __restrict__ dst) {
    int e = blockIdx.x * 256 + threadIdx.x;
    if (e < NE) atomicAdd(&g_deg[dst[e]], 1);
}
__global__ void k_scan() {
    __shared__ int sh[1024];
    int t = threadIdx.x;
    const int chunk = (NN + 1023) / 1024;
    int beg = t * chunk;
    int end = min(beg + chunk, NN);
    int s = 0;
    for (int i = beg; i < end; i++) s += g_deg[i];
    sh[t] = s;
    __syncthreads();
    for (int off = 1; off < 1024; off <<= 1) {
        int v = (t >= off) ? sh[t - off] : 0;
        __syncthreads();
        sh[t] += v;
        __syncthreads();
    }
    int prefix = (t == 0) ? 0 : sh[t - 1];
    for (int i = beg; i < end; i++) {
        g_rowptr[i] = prefix;
        g_cursor[i] = prefix;
        prefix += g_deg[i];
    }
    if (t == 0) g_rowptr[NN] = NE;
}
__global__ void k_scatter(const int* __restrict__ src, const int* __restrict__ dst) {
    int e = blockIdx.x * 256 + threadIdx.x;
    if (e < NE) {
        int d = dst[e];
        int p = atomicAdd(&g_cursor[d], 1);
        g_col[p] = src[e];
    }
}

// ======================= aggregation: warp per node =======================
template <int MODE>  // 0: mean-agg, 1: self + sum-agg (GIN)
__global__ __launch_bounds__(256) void k_agg(const float* __restrict__ X,
                                             float* __restrict__ O) {
    int gw = (blockIdx.x * blockDim.x + threadIdx.x) >> 5;
    if (gw >= NN) return;
    int lane = threadIdx.x & 31;
    int beg = g_rowptr[gw], end = g_rowptr[gw + 1];
    float4 acc = make_float4(0.f, 0.f, 0.f, 0.f);
    for (int eb = beg; eb < end; eb += 32) {
        int n = min(32, end - eb);
        int ci = (eb + lane < end) ? g_col[eb + lane] : 0;
        for (int j = 0; j < n; j++) {
            int s = __shfl_sync(0xffffffffu, ci, j);
            float4 v = __ldg((const float4*)(X + (size_t)s * HD) + lane);
            acc.x += v.x; acc.y += v.y; acc.z += v.z; acc.w += v.w;
        }
    }
    if (MODE == 0) {
        int d = end - beg;
        float dd = (float)(d > 1 ? d : 1);
        acc.x /= dd; acc.y /= dd; acc.z /= dd; acc.w /= dd;
    } else {
        float4 v = __ldg((const float4*)(X + (size_t)gw * HD) + lane);
        acc.x += v.x; acc.y += v.y; acc.z += v.z; acc.w += v.w;
    }
    ((float4*)(O + (size_t)gw * HD))[lane] = acc;
}

// ======================= weight image prep =======================
// W: [128, Nw] row-major. Image: Wt[n][k] bf16 hi/lo, padded row stride 136 ushorts.
__global__ void k_prep_w(const float* __restrict__ W, int Nw,
                         unsigned short* __restrict__ hi, unsigned short* __restrict__ lo) {
    int idx = blockIdx.x * 256 + threadIdx.x;
    if (idx >= Nw * 128) return;
    int n = idx >> 7, k = idx & 127;
    float v = W[(size_t)k * Nw + n];
    __nv_bfloat16 h = __float2bfloat16_rn(v);
    __nv_bfloat16 l = __float2bfloat16_rn(v - __bfloat162float(h));
    int off = n * 136 + k;
    hi[off] = *reinterpret_cast<unsigned short*>(&h);
    lo[off] = *reinterpret_cast<unsigned short*>(&l);
}

// ======================= mma.sync bf16 split GEMM =======================
// C[NN, NWOUT] = A1@W1 (+ A2@W2) + bias, optional ReLU. 3-product bf16 split.
// CTA: 256 threads (8 warps), 128 rows; warp handles 16 rows x all cols.
template <int NT, int NWOUT, bool DUAL, bool RELU>
__global__ __launch_bounds__(256) void k_mma(
    const float* __restrict__ A1,
    const unsigned short* __restrict__ W1h, const unsigned short* __restrict__ W1l,
    const float* __restrict__ A2,
    const unsigned short* __restrict__ W2h, const unsigned short* __restrict__ W2l,
    const float* __restrict__ bias, float* __restrict__ C) {
    extern __shared__ char sm[];
    constexpr int IMG = NT * 8 * 272;  // bytes per image in smem
    const int t = threadIdx.x, w = t >> 5, lane = t & 31;

    // copy W images to smem
    {
        const int n4 = IMG / 16;
        for (int i = t; i < n4; i += 256) {
            ((uint4*)sm)[i] = ((const uint4*)W1h)[i];
            ((uint4*)(sm + IMG))[i] = ((const uint4*)W1l)[i];
        }
        if (DUAL) {
            for (int i = t; i < n4; i += 256) {
                ((uint4*)(sm + 2 * IMG))[i] = ((const uint4*)W2h)[i];
                ((uint4*)(sm + 3 * IMG))[i] = ((const uint4*)W2l)[i];
            }
        }
    }
    __syncthreads();

    const int gid = lane >> 2, tig = lane & 3;
    const int r0 = blockIdx.x * 128 + w * 16 + gid;  // rows r0, r0+8
    const bool ok0 = r0 < NN, ok1 = (r0 + 8) < NN;
    const uint32_t sb = smem_u32(sm);
    // ldmatrix.x4 lane offset within image: m0=(nt0,k0) m1=(nt0,k+8) m2=(nt1,k0) m3=(nt1,k+8)
    const uint32_t laneoff =
        (uint32_t)((((lane >> 4) * 8 + (lane & 7)) * 272) + (((lane >> 3) & 1) * 16));

    float acc[NT][4];
#pragma unroll
    for (int i = 0; i < NT; i++)
#pragma unroll
        for (int j = 0; j < 4; j++) acc[i][j] = 0.f;

    const int npass = DUAL ? 2 : 1;
    for (int pass = 0; pass < npass; ++pass) {
        const float* A = pass ? A2 : A1;
        const float* Ar0 = A + (size_t)r0 * HD + 2 * tig;
        const float* Ar1 = A + (size_t)(r0 + 8) * HD + 2 * tig;
        const uint32_t imgh = sb + (pass ? 2 * IMG : 0);
        const uint32_t imgl = imgh + IMG;
        const float2 z2 = make_float2(0.f, 0.f);
        for (int s = 0; s < 8; ++s) {
            const int k0 = s * 16;
            float2 v0 = ok0 ? __ldg((const float2*)(Ar0 + k0)) : z2;
            float2 v1 = ok1 ? __ldg((const float2*)(Ar1 + k0)) : z2;
            float2 v2 = ok0 ? __ldg((const float2*)(Ar0 + k0 + 8)) : z2;
            float2 v3 = ok1 ? __ldg((const float2*)(Ar1 + k0 + 8)) : z2;
            uint32_t ah[4], al[4];
            splitpair(v0, ah[0], al[0]);
            splitpair(v1, ah[1], al[1]);
            splitpair(v2, ah[2], al[2]);
            splitpair(v3, ah[3], al[3]);
            const uint32_t bh_base = imgh + s * 32 + laneoff;
            const uint32_t bl_base = imgl + s * 32 + laneoff;
#pragma unroll
            for (int p = 0; p < NT / 2; ++p) {
                uint32_t bh[4], bl[4];
                ldsm4(bh, bh_base + p * 4352);
                mma_bf16(acc[2 * p], ah[0], ah[1], ah[2], ah[3], bh[0], bh[1]);
                mma_bf16(acc[2 * p + 1], ah[0], ah[1], ah[2], ah[3], bh[2], bh[3]);
                mma_bf16(acc[2 * p], al[0], al[1], al[2], al[3], bh[0], bh[1]);
                mma_bf16(acc[2 * p + 1], al[0], al[1], al[2], al[3], bh[2], bh[3]);
                ldsm4(bl, bl_base + p * 4352);
                mma_bf16(acc[2 * p], ah[0], ah[1], ah[2], ah[3], bl[0], bl[1]);
                mma_bf16(acc[2 * p + 1], ah[0], ah[1], ah[2], ah[3], bl[2], bl[3]);
            }
        }
    }

    // epilogue
#pragma unroll
    for (int nt = 0; nt < NT; ++nt) {
        int col = nt * 8 + 2 * tig;
        if (col < NWOUT) {
            float2 bv = __ldg((const float2*)(bias + col));
            if (ok0) {
                float2 o = make_float2(acc[nt][0] + bv.x, acc[nt][1] + bv.y);
                if (RELU) { o.x = fmaxf(o.x, 0.f); o.y = fmaxf(o.y, 0.f); }
                *(float2*)(C + (size_t)r0 * NWOUT + col) = o;
            }
            if (ok1) {
                float2 o = make_float2(acc[nt][2] + bv.x, acc[nt][3] + bv.y);
                if (RELU) { o.x = fmaxf(o.x, 0.f); o.y = fmaxf(o.y, 0.f); }
                *(float2*)(C + (size_t)(r0 + 8) * NWOUT + col) = o;
            }
        }
    }
}

// ======================= BatchNorm =======================
__global__ void k_bn_zero() {
    int c = threadIdx.x;
    g_sum[c] = 0.f;
    g_sumsq[c] = 0.f;
}
__global__ __launch_bounds__(256) void k_bn_stats(const float* __restrict__ X) {
    __shared__ float sh[256];
    int t = threadIdx.x;
    int c = t & 127, half = t >> 7;
    int row0 = blockIdx.x * 128;
    float s = 0.f, ss = 0.f;
    for (int i = half; i < 128; i += 2) {
        int r = row0 + i;
        if (r < NN) {
            float v = X[(size_t)r * HD + c];
            s += v;
            ss = fmaf(v, v, ss);
        }
    }
    sh[t] = s;
    __syncthreads();
    if (half == 0) atomicAdd(&g_sum[c], s + sh[128 + c]);
    __syncthreads();
    sh[t] = ss;
    __syncthreads();
    if (half == 0) atomicAdd(&g_sumsq[c], ss + sh[128 + c]);
}
__global__ void k_bn_finalize(const float* __restrict__ gamma,
                              const float* __restrict__ beta, int layer) {
    int c = threadIdx.x;
    float mean = g_sum[c] * (1.0f / NN);
    float var = g_sumsq[c] * (1.0f / NN) - mean * mean;
    float sc = gamma[layer * HD + c] * rsqrtf(var + BN_EPS);
    g_scale[c] = sc;
    g_shift[c] = fmaf(-mean, sc, beta[layer * HD + c]);
}
template <bool RES>
__global__ __launch_bounds__(256) void k_bn_apply(const float* __restrict__ X,
                                                  const float* __restrict__ R,
                                                  float* __restrict__ O) {
    int idx = blockIdx.x * 256 + threadIdx.x;
    if (idx >= NN * 32) return;
    int c4 = idx & 31;
    float4 v = ((const float4*)X)[idx];
    float4 sc = ((const float4*)g_scale)[c4];
    float4 sf = ((const float4*)g_shift)[c4];
    v.x = fmaxf(fmaf(v.x, sc.x, sf.x), 0.f);
    v.y = fmaxf(fmaf(v.y, sc.y, sf.y), 0.f);
    v.z = fmaxf(fmaf(v.z, sc.z, sf.z), 0.f);
    v.w = fmaxf(fmaf(v.w, sc.w, sf.w), 0.f);
    if (RES) {
        float4 r = ((const float4*)R)[idx];
        v.x += r.x; v.y += r.y; v.z += r.z; v.w += r.w;
    }
    ((float4*)O)[idx] = v;
}

// ======================= log_softmax (40 cols) =======================
__global__ __launch_bounds__(256) void k_logsoftmax(const float* __restrict__ X,
                                                    float* __restrict__ O) {
    int w = (blockIdx.x * 256 + threadIdx.x) >> 5;
    if (w >= NN) return;
    int lane = threadIdx.x & 31;
    const float* row = X + (size_t)w * DOUT;
    float v0 = (lane < DOUT) ? row[lane] : -INFINITY;
    float v1 = (lane + 32 < DOUT) ? row[lane + 32] : -INFINITY;
    float m = fmaxf(v0, v1);
#pragma unroll
    for (int o = 16; o; o >>= 1) m = fmaxf(m, __shfl_xor_sync(0xffffffffu, m, o));
    float s = expf(v0 - m) + ((lane + 32 < DOUT) ? expf(v1 - m) : 0.f);
#pragma unroll
    for (int o = 16; o; o >>= 1) s += __shfl_xor_sync(0xffffffffu, s, o);
    float l = m + logf(s);
    if (lane < DOUT) O[(size_t)w * DOUT + lane] = v0 - l;
    if (lane + 32 < DOUT) O[(size_t)w * DOUT + lane + 32] = v1 - l;
}

// ======================= launch =======================
extern "C" void kernel_launch(void* const* d_in, const int* in_sizes, int n_in,
                              void* d_out, int out_size) {
    const float* x    = (const float*)d_in[0];
    const int*   ei   = (const int*)d_in[1];
    const int*   src  = ei;
    const int*   dst  = ei + NE;
    const float* s0wl = (const float*)d_in[2];
    const float* s0wr = (const float*)d_in[3];
    const float* s0b  = (const float*)d_in[4];
    const float* gw1  = (const float*)d_in[5];
    const float* gb1  = (const float*)d_in[6];
    const float* gw2  = (const float*)d_in[7];
    const float* gb2  = (const float*)d_in[8];
    const float* s2wl = (const float*)d_in[9];
    const float* s2wr = (const float*)d_in[10];
    const float* s2b  = (const float*)d_in[11];
    const float* fwl  = (const float*)d_in[12];
    const float* fwr  = (const float*)d_in[13];
    const float* fb   = (const float*)d_in[14];
    const float* gamma = (const float*)d_in[15];
    const float* beta  = (const float*)d_in[16];
    float* out = (float*)d_out;

    void* p;
    cudaGetSymbolAddress(&p, g_bufA); float* A = (float*)p;
    cudaGetSymbolAddress(&p, g_bufB); float* B = (float*)p;
    cudaGetSymbolAddress(&p, g_bufC); float* C = (float*)p;
    cudaGetSymbolAddress(&p, g_wi);   unsigned short* wi = (unsigned short*)p;
    cudaGetSymbolAddress(&p, g_wi40); unsigned short* wi40 = (unsigned short*)p;
    auto WH = [&](int i) { return wi + (size_t)(2 * i + 0) * IMGU; };
    auto WL = [&](int i) { return wi + (size_t)(2 * i + 1) * IMGU; };
    auto W4H = [&](int i) { return wi40 + (size_t)(2 * i + 0) * IMG40U; };
    auto W4L = [&](int i) { return wi40 + (size_t)(2 * i + 1) * IMG40U; };

    const int IMGB = 16 * 8 * 272;      // 34816
    const int IMG40B = 6 * 8 * 272;     // 13056
    const int SMD = 4 * IMGB;           // 139264 (dual 128)
    const int SMS = 2 * IMGB;           // 69632  (single 128)
    const int SM40 = 4 * IMG40B;        // 52224  (dual 40)
    cudaFuncSetAttribute((const void*)k_mma<16, 128, true, false>,
                         cudaFuncAttributeMaxDynamicSharedMemorySize, SMD);
    cudaFuncSetAttribute((const void*)k_mma<16, 128, false, true>,
                         cudaFuncAttributeMaxDynamicSharedMemorySize, SMS);
    cudaFuncSetAttribute((const void*)k_mma<16, 128, false, false>,
                         cudaFuncAttributeMaxDynamicSharedMemorySize, SMS);
    cudaFuncSetAttribute((const void*)k_mma<6, 40, true, false>,
                         cudaFuncAttributeMaxDynamicSharedMemorySize, SM40);

    // weight images (tiny)
    k_prep_w<<<64, 256>>>(s0wl, 128, WH(0), WL(0));
    k_prep_w<<<64, 256>>>(s0wr, 128, WH(1), WL(1));
    k_prep_w<<<64, 256>>>(gw1, 128, WH(2), WL(2));
    k_prep_w<<<64, 256>>>(gw2, 128, WH(3), WL(3));
    k_prep_w<<<64, 256>>>(s2wl, 128, WH(4), WL(4));
    k_prep_w<<<64, 256>>>(s2wr, 128, WH(5), WL(5));
    k_prep_w<<<20, 256>>>(fwl, 40, W4H(0), W4L(0));
    k_prep_w<<<20, 256>>>(fwr, 40, W4H(1), W4L(1));

    // CSR build
    k_zero_deg<<<(NN + 255) / 256, 256>>>();
    k_hist<<<(NE + 255) / 256, 256>>>(dst);
    k_scan<<<1, 1024>>>();
    k_scatter<<<(NE + 255) / 256, 256>>>(src, dst);

    // Layer 0: SAGE(x) -> BN -> ReLU          h := C
    k_agg<0><<<WARP_BLOCKS, 256>>>(x, A);
    k_mma<16, 128, true, false><<<GB, 256, SMD>>>(A, WH(0), WL(0), x, WH(1), WL(1), s0b, B);
    k_bn_zero<<<1, 128>>>();
    k_bn_stats<<<GB, 256>>>(B);
    k_bn_finalize<<<1, 128>>>(gamma, beta, 0);
    k_bn_apply<false><<<WARP_BLOCKS, 256>>>(B, nullptr, C);

    // Layer 1: GIN -> BN -> ReLU -> +res      h := B
    k_agg<1><<<WARP_BLOCKS, 256>>>(C, A);
    k_mma<16, 128, false, true><<<GB, 256, SMS>>>(A, WH(2), WL(2), nullptr, nullptr, nullptr, gb1, B);
    k_mma<16, 128, false, false><<<GB, 256, SMS>>>(B, WH(3), WL(3), nullptr, nullptr, nullptr, gb2, A);
    k_bn_zero<<<1, 128>>>();
    k_bn_stats<<<GB, 256>>>(A);
    k_bn_finalize<<<1, 128>>>(gamma, beta, 1);
    k_bn_apply<true><<<WARP_BLOCKS, 256>>>(A, C, B);

    // Layer 2: SAGE -> BN -> ReLU -> +res     h := A
    k_agg<0><<<WARP_BLOCKS, 256>>>(B, A);
    k_mma<16, 128, true, false><<<GB, 256, SMD>>>(A, WH(4), WL(4), B, WH(5), WL(5), s2b, C);
    k_bn_zero<<<1, 128>>>();
    k_bn_stats<<<GB, 256>>>(C);
    k_bn_finalize<<<1, 128>>>(gamma, beta, 2);
    k_bn_apply<true><<<WARP_BLOCKS, 256>>>(C, B, A);

    // Final: SAGE(H->40) + log_softmax
    k_agg<0><<<WARP_BLOCKS, 256>>>(A, B);
    k_mma<6, 40, true, false><<<GB, 256, SM40>>>(B, W4H(0), W4L(0), A, W4H(1), W4L(1), fb, C);
    k_logsoftmax<<<WARP_BLOCKS, 256>>>(C, out);
}

// round 4
// speedup vs baseline: 1.2622x; 1.0214x over previous
#include <cuda_runtime.h>
#include <cuda_bf16.h>
#include <math.h>
#include <stdint.h>

#define NN 100000
#define NE 1600000
#define HD 128
#define DOUT 40
#define BN_EPS 1e-5f
#define GB 782             // ceil(NN/128)
#define WARP_BLOCKS 12500  // NN*32/256

// ======================= scratch (static device memory) =======================
__device__ __align__(16) float g_bufA[(size_t)NN * HD];
__device__ __align__(16) float g_bufB[(size_t)NN * HD];
__device__ __align__(16) float g_bufC[(size_t)NN * HD];
__device__ int g_deg[NN];
__device__ int g_rowptr[NN + 1];
__device__ int g_cursor[NN];
__device__ int g_col[NE];
__device__ float g_sum3[3 * 128];
__device__ float g_sumsq3[3 * 128];
__device__ __align__(16) float g_scale[HD];
__device__ __align__(16) float g_shift[HD];
// weight images: transposed (Wt[n][k]), bf16, padded rows of 136 ushorts (272 B)
#define IMGU 17408   // 128*136 ushorts
#define IMG40U 6528  // 48*136 ushorts (rows 40..47 stay zero)
__device__ __align__(16) unsigned short g_wi[12 * IMGU];
__device__ __align__(16) unsigned short g_wi40[4 * IMG40U];

// ======================= helpers =======================
__device__ __forceinline__ uint32_t smem_u32(const void* p) {
    uint32_t a;
    asm("{ .reg .u64 t; cvta.to.shared.u64 t, %1; cvt.u32.u64 %0, t; }" : "=r"(a) : "l"(p));
    return a;
}
__device__ __forceinline__ void ldsm4(uint32_t* r, uint32_t addr) {
    asm volatile("ldmatrix.sync.aligned.m8n8.x4.shared.b16 {%0,%1,%2,%3}, [%4];"
                 : "=r"(r[0]), "=r"(r[1]), "=r"(r[2]), "=r"(r[3]) : "r"(addr));
}
__device__ __forceinline__ void mma_bf16(float* c, uint32_t a0, uint32_t a1, uint32_t a2,
                                         uint32_t a3, uint32_t b0, uint32_t b1) {
    asm volatile(
        "mma.sync.aligned.m16n8k16.row.col.f32.bf16.bf16.f32 "
        "{%0,%1,%2,%3}, {%4,%5,%6,%7}, {%8,%9}, {%0,%1,%2,%3};"
        : "+f"(c[0]), "+f"(c[1]), "+f"(c[2]), "+f"(c[3])
        : "r"(a0), "r"(a1), "r"(a2), "r"(a3), "r"(b0), "r"(b1));
}
__device__ __forceinline__ void splitpair(float2 v, uint32_t& h, uint32_t& l) {
    __nv_bfloat162 hb = __float22bfloat162_rn(v);
    float2 hf = __bfloat1622float2(hb);
    __nv_bfloat162 lb = __float22bfloat162_rn(make_float2(v.x - hf.x, v.y - hf.y));
    h = *reinterpret_cast<uint32_t*>(&hb);
    l = *reinterpret_cast<uint32_t*>(&lb);
}

// ======================= CSR build =======================
__global__ void k_zero_deg() {
    int i = blockIdx.x * 256 + threadIdx.x;
    if (i < NN) g_deg[i] = 0;
    if (i < 3 * 128) {
        g_sum3[i] = 0.f;
        g_sumsq3[i] = 0.f;
    }
}
__global__ void k_hist(const int* __restrict__ dst) {
    int e = blockIdx.x * 256 + threadIdx.x;
    if (e < NE) atomicAdd(&g_deg[dst[e]], 1);
}
__global__ void k_scan() {
    __shared__ int sh[1024];
    int t = threadIdx.x;
    const int chunk = (NN + 1023) / 1024;
    int beg = t * chunk;
    int end = min(beg + chunk, NN);
    int s = 0;
    for (int i = beg; i < end; i++) s += g_deg[i];
    sh[t] = s;
    __syncthreads();
    for (int off = 1; off < 1024; off <<= 1) {
        int v = (t >= off) ? sh[t - off] : 0;
        __syncthreads();
        sh[t] += v;
        __syncthreads();
    }
    int prefix = (t == 0) ? 0 : sh[t - 1];
    for (int i = beg; i < end; i++) {
        g_rowptr[i] = prefix;
        g_cursor[i] = prefix;
        prefix += g_deg[i];
    }
    if (t == 0) g_rowptr[NN] = NE;
}
__global__ void k_scatter(const int* __restrict__ src, const int* __restrict__ dst) {
    int e = blockIdx.x * 256 + threadIdx.x;
    if (e < NE) {
        int d = dst[e];
        int p = atomicAdd(&g_cursor[d], 1);
        g_col[p] = src[e];
    }
}

// ======================= aggregation: warp per node =======================
// Direct uniform loads of column indices (no shfl in dependency chain), 4-way MLP.
template <int MODE>  // 0: mean-agg, 1: self + sum-agg (GIN)
__global__ __launch_bounds__(256) void k_agg(const float* __restrict__ X,
                                             float* __restrict__ O) {
    int gw = (blockIdx.x * blockDim.x + threadIdx.x) >> 5;
    if (gw >= NN) return;
    int lane = threadIdx.x & 31;
    int beg = g_rowptr[gw], end = g_rowptr[gw + 1];
    float4 acc = make_float4(0.f, 0.f, 0.f, 0.f);
    int e = beg;
    for (; e + 4 <= end; e += 4) {
        int s0 = __ldg(g_col + e);
        int s1 = __ldg(g_col + e + 1);
        int s2 = __ldg(g_col + e + 2);
        int s3 = __ldg(g_col + e + 3);
        float4 v0 = __ldg((const float4*)(X + (size_t)s0 * HD) + lane);
        float4 v1 = __ldg((const float4*)(X + (size_t)s1 * HD) + lane);
        float4 v2 = __ldg((const float4*)(X + (size_t)s2 * HD) + lane);
        float4 v3 = __ldg((const float4*)(X + (size_t)s3 * HD) + lane);
        acc.x += v0.x + v1.x + v2.x + v3.x;
        acc.y += v0.y + v1.y + v2.y + v3.y;
        acc.z += v0.z + v1.z + v2.z + v3.z;
        acc.w += v0.w + v1.w + v2.w + v3.w;
    }
    for (; e < end; ++e) {
        int s = __ldg(g_col + e);
        float4 v = __ldg((const float4*)(X + (size_t)s * HD) + lane);
        acc.x += v.x; acc.y += v.y; acc.z += v.z; acc.w += v.w;
    }
    if (MODE == 0) {
        int d = end - beg;
        float dd = (float)(d > 1 ? d : 1);
        acc.x /= dd; acc.y /= dd; acc.z /= dd; acc.w /= dd;
    } else {
        float4 v = __ldg((const float4*)(X + (size_t)gw * HD) + lane);
        acc.x += v.x; acc.y += v.y; acc.z += v.z; acc.w += v.w;
    }
    ((float4*)(O + (size_t)gw * HD))[lane] = acc;
}

// ======================= weight image prep (all 8 in one launch) =======================
// W: [128, Nw] row-major. Image: Wt[n][k] bf16 hi/lo, row stride 136 ushorts.
__global__ void k_prep_all(const float* __restrict__ w0, const float* __restrict__ w1,
                           const float* __restrict__ w2, const float* __restrict__ w3,
                           const float* __restrict__ w4, const float* __restrict__ w5,
                           const float* __restrict__ w6, const float* __restrict__ w7) {
    int b = blockIdx.x, t = threadIdx.x;
    const float* W;
    unsigned short *hi, *lo;
    int Nw, idx;
    if (b < 384) {
        int m = b >> 6;
        switch (m) {
            case 0: W = w0; break; case 1: W = w1; break; case 2: W = w2; break;
            case 3: W = w3; break; case 4: W = w4; break; default: W = w5; break;
        }
        hi = g_wi + (size_t)(2 * m + 0) * IMGU;
        lo = g_wi + (size_t)(2 * m + 1) * IMGU;
        Nw = 128;
        idx = (b & 63) * 256 + t;
    } else {
        int mb = b - 384;
        int m = mb / 20;
        W = m ? w7 : w6;
        hi = g_wi40 + (size_t)(2 * m + 0) * IMG40U;
        lo = g_wi40 + (size_t)(2 * m + 1) * IMG40U;
        Nw = 40;
        idx = (mb % 20) * 256 + t;
    }
    if (idx >= Nw * 128) return;
    int n = idx >> 7, k = idx & 127;
    float v = W[(size_t)k * Nw + n];
    __nv_bfloat16 h = __float2bfloat16_rn(v);
    __nv_bfloat16 l = __float2bfloat16_rn(v - __bfloat162float(h));
    int off = n * 136 + k;
    hi[off] = *reinterpret_cast<unsigned short*>(&h);
    lo[off] = *reinterpret_cast<unsigned short*>(&l);
}

// ======================= mma.sync bf16 split GEMM =======================
// C = A1@W1 (+ A2@W2) + bias; optional ReLU; optional fused BN-stats; optional
// fused log_softmax (NWOUT=40 path writes final output directly).
template <int NT, int NWOUT, bool DUAL, bool RELU, bool STATS, bool SMAX>
__global__ __launch_bounds__(256) void k_mma(
    const float* __restrict__ A1,
    const unsigned short* __restrict__ W1h, const unsigned short* __restrict__ W1l,
    const float* __restrict__ A2,
    const unsigned short* __restrict__ W2h, const unsigned short* __restrict__ W2l,
    const float* __restrict__ bias, float* __restrict__ C, int layer) {
    extern __shared__ char sm[];
    __shared__ float ssum[128], ssq[128];
    constexpr int IMG = NT * 8 * 272;  // bytes per image in smem
    const int t = threadIdx.x, w = t >> 5, lane = t & 31;

    if (STATS && t < 128) {
        ssum[t] = 0.f;
        ssq[t] = 0.f;
    }
    // copy W images to smem
    {
        const int n4 = IMG / 16;
        for (int i = t; i < n4; i += 256) {
            ((uint4*)sm)[i] = ((const uint4*)W1h)[i];
            ((uint4*)(sm + IMG))[i] = ((const uint4*)W1l)[i];
        }
        if (DUAL) {
            for (int i = t; i < n4; i += 256) {
                ((uint4*)(sm + 2 * IMG))[i] = ((const uint4*)W2h)[i];
                ((uint4*)(sm + 3 * IMG))[i] = ((const uint4*)W2l)[i];
            }
        }
    }
    __syncthreads();

    const int gid = lane >> 2, tig = lane & 3;
    const int r0 = blockIdx.x * 128 + w * 16 + gid;  // rows r0, r0+8
    const bool ok0 = r0 < NN, ok1 = (r0 + 8) < NN;
    const uint32_t sb = smem_u32(sm);
    const uint32_t laneoff =
        (uint32_t)((((lane >> 4) * 8 + (lane & 7)) * 272) + (((lane >> 3) & 1) * 16));

    float acc[NT][4];
#pragma unroll
    for (int i = 0; i < NT; i++)
#pragma unroll
        for (int j = 0; j < 4; j++) acc[i][j] = 0.f;

    const int npass = DUAL ? 2 : 1;
    for (int pass = 0; pass < npass; ++pass) {
        const float* A = pass ? A2 : A1;
        const float* Ar0 = A + (size_t)r0 * HD + 2 * tig;
        const float* Ar1 = A + (size_t)(r0 + 8) * HD + 2 * tig;
        const uint32_t imgh = sb + (pass ? 2 * IMG : 0);
        const uint32_t imgl = imgh + IMG;
        const float2 z2 = make_float2(0.f, 0.f);
        for (int s = 0; s < 8; ++s) {
            const int k0 = s * 16;
            float2 v0 = ok0 ? __ldg((const float2*)(Ar0 + k0)) : z2;
            float2 v1 = ok1 ? __ldg((const float2*)(Ar1 + k0)) : z2;
            float2 v2 = ok0 ? __ldg((const float2*)(Ar0 + k0 + 8)) : z2;
            float2 v3 = ok1 ? __ldg((const float2*)(Ar1 + k0 + 8)) : z2;
            uint32_t ah[4], al[4];
            splitpair(v0, ah[0], al[0]);
            splitpair(v1, ah[1], al[1]);
            splitpair(v2, ah[2], al[2]);
            splitpair(v3, ah[3], al[3]);
            const uint32_t bh_base = imgh + s * 32 + laneoff;
            const uint32_t bl_base = imgl + s * 32 + laneoff;
#pragma unroll
            for (int p = 0; p < NT / 2; ++p) {
                uint32_t bh[4], bl[4];
                ldsm4(bh, bh_base + p * 4352);
                mma_bf16(acc[2 * p], ah[0], ah[1], ah[2], ah[3], bh[0], bh[1]);
                mma_bf16(acc[2 * p + 1], ah[0], ah[1], ah[2], ah[3], bh[2], bh[3]);
                mma_bf16(acc[2 * p], al[0], al[1], al[2], al[3], bh[0], bh[1]);
                mma_bf16(acc[2 * p + 1], al[0], al[1], al[2], al[3], bh[2], bh[3]);
                ldsm4(bl, bl_base + p * 4352);
                mma_bf16(acc[2 * p], ah[0], ah[1], ah[2], ah[3], bl[0], bl[1]);
                mma_bf16(acc[2 * p + 1], ah[0], ah[1], ah[2], ah[3], bl[2], bl[3]);
            }
        }
    }

    // ============== epilogue ==============
    if (SMAX) {
        // final layer: 40 cols; nt 0..4 valid. Fused log_softmax, write output.
        float o0x[5], o0y[5], o1x[5], o1y[5];
        float m0 = -INFINITY, m1 = -INFINITY;
#pragma unroll
        for (int nt = 0; nt < 5; ++nt) {
            int col = nt * 8 + 2 * tig;
            float2 bv = __ldg((const float2*)(bias + col));
            o0x[nt] = acc[nt][0] + bv.x;
            o0y[nt] = acc[nt][1] + bv.y;
            o1x[nt] = acc[nt][2] + bv.x;
            o1y[nt] = acc[nt][3] + bv.y;
            m0 = fmaxf(m0, fmaxf(o0x[nt], o0y[nt]));
            m1 = fmaxf(m1, fmaxf(o1x[nt], o1y[nt]));
        }
        m0 = fmaxf(m0, __shfl_xor_sync(0xffffffffu, m0, 1));
        m0 = fmaxf(m0, __shfl_xor_sync(0xffffffffu, m0, 2));
        m1 = fmaxf(m1, __shfl_xor_sync(0xffffffffu, m1, 1));
        m1 = fmaxf(m1, __shfl_xor_sync(0xffffffffu, m1, 2));
        float s0 = 0.f, s1 = 0.f;
#pragma unroll
        for (int nt = 0; nt < 5; ++nt) {
            s0 += expf(o0x[nt] - m0) + expf(o0y[nt] - m0);
            s1 += expf(o1x[nt] - m1) + expf(o1y[nt] - m1);
        }
        s0 += __shfl_xor_sync(0xffffffffu, s0, 1);
        s0 += __shfl_xor_sync(0xffffffffu, s0, 2);
        s1 += __shfl_xor_sync(0xffffffffu, s1, 1);
        s1 += __shfl_xor_sync(0xffffffffu, s1, 2);
        float l0 = m0 + logf(s0), l1 = m1 + logf(s1);
#pragma unroll
        for (int nt = 0; nt < 5; ++nt) {
            int col = nt * 8 + 2 * tig;
            if (ok0)
                *(float2*)(C + (size_t)r0 * DOUT + col) =
                    make_float2(o0x[nt] - l0, o0y[nt] - l0);
            if (ok1)
                *(float2*)(C + (size_t)(r0 + 8) * DOUT + col) =
                    make_float2(o1x[nt] - l1, o1y[nt] - l1);
        }
    } else {
#pragma unroll
        for (int nt = 0; nt < NT; ++nt) {
            int col = nt * 8 + 2 * tig;
            float2 bv = __ldg((const float2*)(bias + col));
            float2 o0 = make_float2(acc[nt][0] + bv.x, acc[nt][1] + bv.y);
            float2 o1 = make_float2(acc[nt][2] + bv.x, acc[nt][3] + bv.y);
            if (RELU) {
                o0.x = fmaxf(o0.x, 0.f); o0.y = fmaxf(o0.y, 0.f);
                o1.x = fmaxf(o1.x, 0.f); o1.y = fmaxf(o1.y, 0.f);
            }
            if (ok0) *(float2*)(C + (size_t)r0 * NWOUT + col) = o0;
            if (ok1) *(float2*)(C + (size_t)(r0 + 8) * NWOUT + col) = o1;
            if (STATS) {
                float sx = (ok0 ? o0.x : 0.f) + (ok1 ? o1.x : 0.f);
                float sy = (ok0 ? o0.y : 0.f) + (ok1 ? o1.y : 0.f);
                float qx = (ok0 ? o0.x * o0.x : 0.f) + (ok1 ? o1.x * o1.x : 0.f);
                float qy = (ok0 ? o0.y * o0.y : 0.f) + (ok1 ? o1.y * o1.y : 0.f);
#pragma unroll
                for (int off = 4; off <= 16; off <<= 1) {
                    sx += __shfl_xor_sync(0xffffffffu, sx, off);
                    sy += __shfl_xor_sync(0xffffffffu, sy, off);
                    qx += __shfl_xor_sync(0xffffffffu, qx, off);
                    qy += __shfl_xor_sync(0xffffffffu, qy, off);
                }
                if (gid == 0) {
                    atomicAdd(&ssum[col], sx);
                    atomicAdd(&ssum[col + 1], sy);
                    atomicAdd(&ssq[col], qx);
                    atomicAdd(&ssq[col + 1], qy);
                }
            }
        }
        if (STATS) {
            __syncthreads();
            if (t < 128) {
                atomicAdd(&g_sum3[layer * 128 + t], ssum[t]);
                atomicAdd(&g_sumsq3[layer * 128 + t], ssq[t]);
            }
        }
    }
}

// ======================= BatchNorm finalize + apply =======================
__global__ void k_bn_finalize(const float* __restrict__ gamma,
                              const float* __restrict__ beta, int layer) {
    int c = threadIdx.x;
    float mean = g_sum3[layer * 128 + c] * (1.0f / NN);
    float var = g_sumsq3[layer * 128 + c] * (1.0f / NN) - mean * mean;
    float sc = gamma[layer * HD + c] * rsqrtf(var + BN_EPS);
    g_scale[c] = sc;
    g_shift[c] = fmaf(-mean, sc, beta[layer * HD + c]);
}
template <bool RES>
__global__ __launch_bounds__(256) void k_bn_apply(const float* __restrict__ X,
                                                  const float* __restrict__ R,
                                                  float* __restrict__ O) {
    int idx = blockIdx.x * 256 + threadIdx.x;
    if (idx >= NN * 32) return;
    int c4 = idx & 31;
    float4 v = ((const float4*)X)[idx];
    float4 sc = ((const float4*)g_scale)[c4];
    float4 sf = ((const float4*)g_shift)[c4];
    v.x = fmaxf(fmaf(v.x, sc.x, sf.x), 0.f);
    v.y = fmaxf(fmaf(v.y, sc.y, sf.y), 0.f);
    v.z = fmaxf(fmaf(v.z, sc.z, sf.z), 0.f);
    v.w = fmaxf(fmaf(v.w, sc.w, sf.w), 0.f);
    if (RES) {
        float4 r = ((const float4*)R)[idx];
        v.x += r.x; v.y += r.y; v.z += r.z; v.w += r.w;
    }
    ((float4*)O)[idx] = v;
}

// ======================= launch =======================
extern "C" void kernel_launch(void* const* d_in, const int* in_sizes, int n_in,
                              void* d_out, int out_size) {
    const float* x    = (const float*)d_in[0];
    const int*   ei   = (const int*)d_in[1];
    const int*   src  = ei;
    const int*   dst  = ei + NE;
    const float* s0wl = (const float*)d_in[2];
    const float* s0wr = (const float*)d_in[3];
    const float* s0b  = (const float*)d_in[4];
    const float* gw1  = (const float*)d_in[5];
    const float* gb1  = (const float*)d_in[6];
    const float* gw2  = (const float*)d_in[7];
    const float* gb2  = (const float*)d_in[8];
    const float* s2wl = (const float*)d_in[9];
    const float* s2wr = (const float*)d_in[10];
    const float* s2b  = (const float*)d_in[11];
    const float* fwl  = (const float*)d_in[12];
    const float* fwr  = (const float*)d_in[13];
    const float* fb   = (const float*)d_in[14];
    const float* gamma = (const float*)d_in[15];
    const float* beta  = (const float*)d_in[16];
    float* out = (float*)d_out;

    void* p;
    cudaGetSymbolAddress(&p, g_bufA); float* A = (float*)p;
    cudaGetSymbolAddress(&p, g_bufB); float* B = (float*)p;
    cudaGetSymbolAddress(&p, g_bufC); float* C = (float*)p;
    cudaGetSymbolAddress(&p, g_wi);   unsigned short* wi = (unsigned short*)p;
    cudaGetSymbolAddress(&p, g_wi40); unsigned short* wi40 = (unsigned short*)p;
    auto WH = [&](int i) { return wi + (size_t)(2 * i + 0) * IMGU; };
    auto WL = [&](int i) { return wi + (size_t)(2 * i + 1) * IMGU; };
    auto W4H = [&](int i) { return wi40 + (size_t)(2 * i + 0) * IMG40U; };
    auto W4L = [&](int i) { return wi40 + (size_t)(2 * i + 1) * IMG40U; };

    const int IMGB = 16 * 8 * 272;   // 34816
    const int IMG40B = 6 * 8 * 272;  // 13056
    const int SMD = 4 * IMGB;        // 139264 (dual 128)
    const int SMS = 2 * IMGB;        // 69632  (single 128)
    const int SM40 = 4 * IMG40B;     // 52224  (dual 40)
    cudaFuncSetAttribute((const void*)k_mma<16, 128, true, false, true, false>,
                         cudaFuncAttributeMaxDynamicSharedMemorySize, SMD);
    cudaFuncSetAttribute((const void*)k_mma<16, 128, false, true, false, false>,
                         cudaFuncAttributeMaxDynamicSharedMemorySize, SMS);
    cudaFuncSetAttribute((const void*)k_mma<16, 128, false, false, true, false>,
                         cudaFuncAttributeMaxDynamicSharedMemorySize, SMS);
    cudaFuncSetAttribute((const void*)k_mma<6, 40, true, false, false, true>,
                         cudaFuncAttributeMaxDynamicSharedMemorySize, SM40);

    // weight images (single launch) + CSR build
    k_prep_all<<<424, 256>>>(s0wl, s0wr, gw1, gw2, s2wl, s2wr, fwl, fwr);
    k_zero_deg<<<(NN + 255) / 256, 256>>>();
    k_hist<<<(NE + 255) / 256, 256>>>(dst);
    k_scan<<<1, 1024>>>();
    k_scatter<<<(NE + 255) / 256, 256>>>(src, dst);

    // Layer 0: SAGE(x) -> BN -> ReLU          h := C
    k_agg<0><<<WARP_BLOCKS, 256>>>(x, A);
    k_mma<16, 128, true, false, true, false><<<GB, 256, SMD>>>(
        A, WH(0), WL(0), x, WH(1), WL(1), s0b, B, 0);
    k_bn_finalize<<<1, 128>>>(gamma, beta, 0);
    k_bn_apply<false><<<WARP_BLOCKS, 256>>>(B, nullptr, C);

    // Layer 1: GIN -> BN -> ReLU -> +res      h := B
    k_agg<1><<<WARP_BLOCKS, 256>>>(C, A);
    k_mma<16, 128, false, true, false, false><<<GB, 256, SMS>>>(
        A, WH(2), WL(2), nullptr, nullptr, nullptr, gb1, B, 0);
    k_mma<16, 128, false, false, true, false><<<GB, 256, SMS>>>(
        B, WH(3), WL(3), nullptr, nullptr, nullptr, gb2, A, 1);
    k_bn_finalize<<<1, 128>>>(gamma, beta, 1);
    k_bn_apply<true><<<WARP_BLOCKS, 256>>>(A, C, B);

    // Layer 2: SAGE -> BN -> ReLU -> +res     h := A
    k_agg<0><<<WARP_BLOCKS, 256>>>(B, A);
    k_mma<16, 128, true, false, true, false><<<GB, 256, SMD>>>(
        A, WH(4), WL(4), B, WH(5), WL(5), s2b, C, 2);
    k_bn_finalize<<<1, 128>>>(gamma, beta, 2);
    k_bn_apply<true><<<WARP_BLOCKS, 256>>>(C, B, A);

    // Final: SAGE(H->40) + fused log_softmax -> out
    k_agg<0><<<WARP_BLOCKS, 256>>>(A, B);
    k_mma<6, 40, true, false, false, true><<<GB, 256, SM40>>>(
        B, W4H(0), W4L(0), A, W4H(1), W4L(1), fb, out, 0);
}